// round 15
// baseline (speedup 1.0000x reference)
#include <cuda_runtime.h>
#include <math.h>

#define DM      512
#define SEQL    1024
#define NCH     8192
#define CHB     4         // channels per block (2 blocks/SM)
#define TOPK    13
#define NTHREADS 256
#define ZS      1025      // float2 stride per channel
#define VSTR    2052      // padded float stride for V tile (>= 2047, ==4 mod 32)
#define OTS     2050      // float stride for output staging (== ZS*2)

// per-channel barrier: 64 threads (2 warps) of channel ch
#define BAR_CH() asm volatile("bar.sync %0, %1;" :: "r"(ch + 1), "r"(64) : "memory")

__device__ __forceinline__ float2 cmul(float2 a, float2 b) {
    return make_float2(a.x * b.x - a.y * b.y, a.x * b.y + a.y * b.x);
}
// XOR swizzle, 5-bit key
__device__ __forceinline__ int sw(int p) { return p ^ ((p >> 4) & 31); }

// ---- packed f32x2 complex add/sub (sm_100+): one instruction per complex op ----
__device__ __forceinline__ float2 fadd2(float2 a, float2 b) {
    float2 r;
    asm("add.rn.f32x2 %0, %1, %2;"
        : "=l"(reinterpret_cast<unsigned long long&>(r))
        : "l"(reinterpret_cast<unsigned long long&>(a)),
          "l"(reinterpret_cast<unsigned long long&>(b)));
    return r;
}
__device__ __forceinline__ float2 fsub2(float2 a, float2 b) {
    float2 r;
    asm("sub.rn.f32x2 %0, %1, %2;"
        : "=l"(reinterpret_cast<unsigned long long&>(r))
        : "l"(reinterpret_cast<unsigned long long&>(a)),
          "l"(reinterpret_cast<unsigned long long&>(b)));
    return r;
}

// powers W[1..15] from w1 via squaring chain (tree depth 4 -> ILP)
__device__ __forceinline__ void twpow(float2 w1, float2* W) {
    W[1] = w1;
    W[2] = cmul(w1, w1);
    W[4] = cmul(W[2], W[2]);
    W[8] = cmul(W[4], W[4]);
    W[3] = cmul(W[2], W[1]);
    W[5] = cmul(W[4], W[1]);
    W[6] = cmul(W[4], W[2]);
    W[7] = cmul(W[4], W[3]);
    W[9]  = cmul(W[8], W[1]);
    W[10] = cmul(W[8], W[2]);
    W[11] = cmul(W[8], W[3]);
    W[12] = cmul(W[8], W[4]);
    W[13] = cmul(W[8], W[5]);
    W[14] = cmul(W[8], W[6]);
    W[15] = cmul(W[8], W[7]);
}

#define C16 0.9238795325112867f
#define S16 0.3826834323650898f
#define R22 0.7071067811865476f

// forward 4-pt DFT (W4 = -i), packed
__device__ __forceinline__ void dft4f(float2 x0, float2 x1, float2 x2, float2 x3,
                                      float2& y0, float2& y1, float2& y2, float2& y3) {
    float2 sp = fadd2(x0, x2);
    float2 sm = fsub2(x0, x2);
    float2 tp = fadd2(x1, x3);
    float2 tm = fsub2(x1, x3);
    y0 = fadd2(sp, tp);
    y2 = fsub2(sp, tp);
    float2 tn = make_float2(tm.y, -tm.x);   // -i * tm
    y1 = fadd2(sm, tn);                     // sm - i*tm
    y3 = fsub2(sm, tn);                     // sm + i*tm
}
// inverse 4-pt DFT (W4 = +i), packed
__device__ __forceinline__ void dft4i(float2 x0, float2 x1, float2 x2, float2 x3,
                                      float2& y0, float2& y1, float2& y2, float2& y3) {
    float2 sp = fadd2(x0, x2);
    float2 sm = fsub2(x0, x2);
    float2 tp = fadd2(x1, x3);
    float2 tm = fsub2(x1, x3);
    y0 = fadd2(sp, tp);
    y2 = fsub2(sp, tp);
    float2 tn = make_float2(-tm.y, tm.x);   // +i * tm
    y1 = fadd2(sm, tn);                     // sm + i*tm
    y3 = fsub2(sm, tn);                     // sm - i*tm
}

// 16-pt DFT in registers, natural order in/out. fwd: e^{-2pi i a f/16}
__device__ __forceinline__ void dft16f(float2* v) {
    const float2 W[10] = {
        { 1.f, 0.f}, { C16,-S16}, { R22,-R22}, { S16,-C16}, { 0.f,-1.f},
        {-S16,-C16}, {-R22,-R22}, {-C16,-S16}, {-1.f, 0.f}, {-C16, S16}
    };
    float2 u[16];
    #pragma unroll
    for (int a0 = 0; a0 < 4; ++a0) {
        float2 t0, t1, t2, t3;
        dft4f(v[a0], v[a0 + 4], v[a0 + 8], v[a0 + 12], t0, t1, t2, t3);
        u[a0 * 4 + 0] = t0;
        u[a0 * 4 + 1] = cmul(t1, W[a0]);
        u[a0 * 4 + 2] = cmul(t2, W[2 * a0]);
        u[a0 * 4 + 3] = cmul(t3, W[3 * a0]);
    }
    #pragma unroll
    for (int fl = 0; fl < 4; ++fl) {
        float2 y0, y1, y2, y3;
        dft4f(u[0 * 4 + fl], u[1 * 4 + fl], u[2 * 4 + fl], u[3 * 4 + fl], y0, y1, y2, y3);
        v[fl]      = y0;
        v[fl + 4]  = y1;
        v[fl + 8]  = y2;
        v[fl + 12] = y3;
    }
}
// inverse 16-pt: e^{+2pi i a f/16}, unnormalized
__device__ __forceinline__ void dft16i(float2* v) {
    const float2 W[10] = {
        { 1.f, 0.f}, { C16, S16}, { R22, R22}, { S16, C16}, { 0.f, 1.f},
        {-S16, C16}, {-R22, R22}, {-C16, S16}, {-1.f, 0.f}, {-C16,-S16}
    };
    float2 u[16];
    #pragma unroll
    for (int fl = 0; fl < 4; ++fl) {
        float2 t0, t1, t2, t3;
        dft4i(v[fl], v[fl + 4], v[fl + 8], v[fl + 12], t0, t1, t2, t3);
        u[fl * 4 + 0] = t0;
        u[fl * 4 + 1] = cmul(t1, W[fl]);
        u[fl * 4 + 2] = cmul(t2, W[2 * fl]);
        u[fl * 4 + 3] = cmul(t3, W[3 * fl]);
    }
    #pragma unroll
    for (int a0 = 0; a0 < 4; ++a0) {
        float2 y0, y1, y2, y3;
        dft4i(u[0 * 4 + a0], u[1 * 4 + a0], u[2 * 4 + a0], u[3 * 4 + a0], y0, y1, y2, y3);
        v[a0]      = y0;
        v[a0 + 4]  = y1;
        v[a0 + 8]  = y2;
        v[a0 + 12] = y3;
    }
}

// W64^mp twiddle, mp in [0,4), via select chain (no MUFU)
__device__ __forceinline__ float2 w64(int mp, float sgn) {
    float c = (mp == 0) ? 1.0f
            : (mp == 1) ? 0.99518472667219693f
            : (mp == 2) ? 0.98078528040323044f
            :             0.95694033573220882f;
    float s = (mp == 0) ? 0.0f
            : (mp == 1) ? 0.09801714032956060f
            : (mp == 2) ? 0.19509032201612827f
            :             0.29028467725446233f;
    return make_float2(c, sgn * s);
}

extern __shared__ float2 smem_dyn[];

__global__ void __launch_bounds__(NTHREADS, 2) autocorr_fused_kernel(
    const float* __restrict__ Q, const float* __restrict__ K,
    const float* __restrict__ V, float* __restrict__ out)
{
    float2* z = smem_dyn;                       // [CHB][ZS]
    float*  vf = (float*)(smem_dyn + CHB * ZS); // [CHB][VSTR], clamp-padded
    __shared__ float2 cand[CHB][2][2];
    __shared__ float  w_sh[CHB][TOPK + 1];
    __shared__ int    i_sh[CHB][TOPK];

    const int tid = threadIdx.x;
    const int ch  = tid >> 6;                   // 0..3
    const int u   = tid & 63;
    float2* zc = z + ch * ZS;

    const int bc0 = blockIdx.x * CHB;
    const int b   = bc0 >> 9;
    const int c0  = bc0 & (DM - 1);
    const size_t base = (size_t)b * SEQL * DM + c0;

    // ---- load: z = q + i*k (swizzled), prefetch V ----
    for (int t = tid; t < SEQL; t += NTHREADS) {
        size_t off = base + (size_t)t * DM;
        float4 q4 = *(const float4*)(Q + off);
        float4 k4 = *(const float4*)(K + off);
        int st = sw(t);
        z[0 * ZS + st] = make_float2(q4.x, k4.x);
        z[1 * ZS + st] = make_float2(q4.y, k4.y);
        z[2 * ZS + st] = make_float2(q4.z, k4.z);
        z[3 * ZS + st] = make_float2(q4.w, k4.w);
        float4 v4 = *(const float4*)(V + off);
        vf[0 * VSTR + t] = v4.x;
        vf[1 * VSTR + t] = v4.y;
        vf[2 * VSTR + t] = v4.z;
        vf[3 * VSTR + t] = v4.w;
    }
    __syncthreads();   // cross-channel: loader wrote all channels

    // ---- clamp-fill V tail: vf[ch][1024..2047] = V[ch][1023] ----
    {
        float vlast = vf[ch * VSTR + (SEQL - 1)];
        float* vt = vf + ch * VSTR + SEQL;
        #pragma unroll
        for (int j = 0; j < 16; ++j) vt[u + 64 * j] = vlast;
    }

    // ---- P1: radix-16 over stride 64, twiddle W1024^{u*f0} ----
    {
        float2 v[16];
        #pragma unroll
        for (int a = 0; a < 16; ++a) v[a] = zc[sw(u + 64 * a)];
        dft16f(v);
        float s, c;
        sincospif((float)u * (1.0f / 512.0f), &s, &c);
        float2 W[16];
        twpow(make_float2(c, -s), W);
        #pragma unroll
        for (int f = 1; f < 16; ++f) v[f] = cmul(v[f], W[f]);
        #pragma unroll
        for (int f = 0; f < 16; ++f) zc[sw(u + 64 * f)] = v[f];
    }
    BAR_CH();

    // ---- P2: radix-16 over stride 4 within 64-blocks, twiddle W64^{m'*f1} ----
    {
        const int blk = u >> 2;
        const int mp  = u & 3;
        const int bas = 64 * blk + mp;
        float2 v[16];
        #pragma unroll
        for (int a = 0; a < 16; ++a) v[a] = zc[sw(bas + 4 * a)];
        dft16f(v);
        float2 W[16];
        twpow(w64(mp, -1.0f), W);
        #pragma unroll
        for (int f = 1; f < 16; ++f) v[f] = cmul(v[f], W[f]);
        #pragma unroll
        for (int f = 0; f < 16; ++f) zc[sw(bas + 4 * f)] = v[f];
    }
    BAR_CH();

    // ---- FUSED: fwd radix-4 + cross-spectrum + inv radix-4, all in registers ----
    // Quad for coefficient c lives at swizzled addrs sw(4g)^k, g = digitswap(c);
    // sw(4g+k) == sw(4g)^k since the XOR key depends only on bits >= 4.
    {
        const float scl = 1.0f / (float)SEQL;
        #pragma unroll
        for (int unit = 0; unit < 2; ++unit) {
            int c = u + 1 + unit * 64;          // [1,64] / [65,128]
            if (c < 128) {
                int cp = 256 - c;
                int pA = sw((((c  & 15) << 4) | (c  >> 4)) << 2);
                int pB = sw((((cp & 15) << 4) | (cp >> 4)) << 2);
                float2 A[4], B[4];
                dft4f(zc[pA], zc[pA^1], zc[pA^2], zc[pA^3], A[0], A[1], A[2], A[3]);
                dft4f(zc[pB], zc[pB^1], zc[pB^2], zc[pB^3], B[0], B[1], B[2], B[3]);
                #pragma unroll
                for (int k = 0; k < 4; ++k) {
                    float2 Zf = A[k], Zp = B[3 - k];
                    float Qx = 0.5f * (Zf.x + Zp.x), Qy = 0.5f * (Zf.y - Zp.y);
                    float Kx = 0.5f * (Zf.y + Zp.y), Ky = -0.5f * (Zf.x - Zp.x);
                    float Px = (Qx * Kx + Qy * Ky) * scl;
                    float Py = (Qy * Kx - Qx * Ky) * scl;
                    A[k]     = make_float2(Px,  Py);
                    B[3 - k] = make_float2(Px, -Py);
                }
                float2 y0, y1, y2, y3;
                dft4i(A[0], A[1], A[2], A[3], y0, y1, y2, y3);
                zc[pA] = y0; zc[pA^1] = y1; zc[pA^2] = y2; zc[pA^3] = y3;
                dft4i(B[0], B[1], B[2], B[3], y0, y1, y2, y3);
                zc[pB] = y0; zc[pB^1] = y1; zc[pB^2] = y2; zc[pB^3] = y3;
            } else {
                // u==63, unit==1: c=128 self-paired quad (g=8, p=32)
                {
                    int pA = sw(32);
                    float2 A[4];
                    dft4f(zc[pA], zc[pA^1], zc[pA^2], zc[pA^3], A[0], A[1], A[2], A[3]);
                    #pragma unroll
                    for (int k = 0; k < 2; ++k) {
                        float2 Zf = A[k], Zp = A[3 - k];
                        float Qx = 0.5f * (Zf.x + Zp.x), Qy = 0.5f * (Zf.y - Zp.y);
                        float Kx = 0.5f * (Zf.y + Zp.y), Ky = -0.5f * (Zf.x - Zp.x);
                        float Px = (Qx * Kx + Qy * Ky) * scl;
                        float Py = (Qy * Kx - Qx * Ky) * scl;
                        A[k]     = make_float2(Px,  Py);
                        A[3 - k] = make_float2(Px, -Py);
                    }
                    float2 y0, y1, y2, y3;
                    dft4i(A[0], A[1], A[2], A[3], y0, y1, y2, y3);
                    zc[pA] = y0; zc[pA^1] = y1; zc[pA^2] = y2; zc[pA^3] = y3;
                }
                // c=0 quad (g=0, p=0, sw key 0): f={0,256,512,768}
                {
                    float2 A[4];
                    dft4f(zc[0], zc[1], zc[2], zc[3], A[0], A[1], A[2], A[3]);
                    A[0] = make_float2(A[0].x * A[0].y * scl, 0.0f);
                    A[2] = make_float2(A[2].x * A[2].y * scl, 0.0f);
                    {
                        float2 Zf = A[1], Zp = A[3];
                        float Qx = 0.5f * (Zf.x + Zp.x), Qy = 0.5f * (Zf.y - Zp.y);
                        float Kx = 0.5f * (Zf.y + Zp.y), Ky = -0.5f * (Zf.x - Zp.x);
                        float Px = (Qx * Kx + Qy * Ky) * scl;
                        float Py = (Qy * Kx - Qx * Ky) * scl;
                        A[1] = make_float2(Px,  Py);
                        A[3] = make_float2(Px, -Py);
                    }
                    float2 y0, y1, y2, y3;
                    dft4i(A[0], A[1], A[2], A[3], y0, y1, y2, y3);
                    zc[0] = y0; zc[1] = y1; zc[2] = y2; zc[3] = y3;
                }
            }
        }
    }
    BAR_CH();

    // ---- IP2: conj twiddle then inverse radix-16 stride 4 ----
    {
        const int blk = u >> 2;
        const int mp  = u & 3;
        const int bas = 64 * blk + mp;
        float2 v[16];
        #pragma unroll
        for (int f = 0; f < 16; ++f) v[f] = zc[sw(bas + 4 * f)];
        float2 W[16];
        twpow(w64(mp, 1.0f), W);
        #pragma unroll
        for (int f = 1; f < 16; ++f) v[f] = cmul(v[f], W[f]);
        dft16i(v);
        #pragma unroll
        for (int a = 0; a < 16; ++a) zc[sw(bas + 4 * a)] = v[a];
    }
    BAR_CH();

    // ---- IP1: conj twiddle then inverse radix-16 stride 64; results stay in regs ----
    float re[16];
    {
        float2 v[16];
        #pragma unroll
        for (int f = 0; f < 16; ++f) v[f] = zc[sw(u + 64 * f)];
        float s, c;
        sincospif((float)u * (1.0f / 512.0f), &s, &c);
        float2 W[16];
        twpow(make_float2(c, s), W);
        #pragma unroll
        for (int f = 1; f < 16; ++f) v[f] = cmul(v[f], W[f]);
        dft16i(v);
        #pragma unroll
        for (int a = 0; a < 16; ++a) re[a] = v[a].x;   // time index = u + 64a
    }

    // ---- top-13: register-resident, 2 warps per channel, named barriers ----
    {
        const int lane = tid & 31;
        const int wih  = (u >> 5) & 1;
        float lv = re[0]; int lj = 0;
        #pragma unroll
        for (int j2 = 1; j2 < 16; ++j2)
            if (re[j2] > lv) { lv = re[j2]; lj = j2; }
        int li = u + 64 * lj;

        #pragma unroll 1
        for (int r = 0; r < TOPK; ++r) {
            float bv = lv; int bi = li;
            #pragma unroll
            for (int off = 16; off; off >>= 1) {
                float ov = __shfl_down_sync(0xffffffffu, bv, off);
                int   oi = __shfl_down_sync(0xffffffffu, bi, off);
                if (ov > bv || (ov == bv && oi < bi)) { bv = ov; bi = oi; }
            }
            bv = __shfl_sync(0xffffffffu, bv, 0);
            bi = __shfl_sync(0xffffffffu, bi, 0);
            int par = r & 1;
            if (lane == 0)
                cand[ch][wih][par] = make_float2(bv, __int_as_float(bi));
            BAR_CH();
            float2 c0v = cand[ch][0][par];
            float2 c1v = cand[ch][1][par];
            float wv; int wi;
            int i0 = __float_as_int(c0v.y), i1 = __float_as_int(c1v.y);
            if (c1v.x > c0v.x || (c1v.x == c0v.x && i1 < i0)) { wv = c1v.x; wi = i1; }
            else                                              { wv = c0v.x; wi = i0; }
            if (u == 0) { w_sh[ch][r] = wv; i_sh[ch][r] = wi; }
            if ((wi & 63) == u) {
                re[wi >> 6] = -INFINITY;
                lv = re[0]; lj = 0;
                #pragma unroll
                for (int j2 = 1; j2 < 16; ++j2)
                    if (re[j2] > lv) { lv = re[j2]; lj = j2; }
                li = u + 64 * lj;
            }
        }
        BAR_CH();
        if (u == 0) {
            float m = -INFINITY;
            #pragma unroll
            for (int i = 0; i < TOPK; ++i) m = fmaxf(m, w_sh[ch][i]);
            float e[TOPK]; float ssum = 0.0f;
            #pragma unroll
            for (int i = 0; i < TOPK; ++i) { e[i] = expf(w_sh[ch][i] - m); ssum += e[i]; }
            float inv = 1.0f / ssum;
            #pragma unroll
            for (int i = 0; i < TOPK; ++i) w_sh[ch][i] = e[i] * inv;
        }
    }
    BAR_CH();   // channel's softmax results visible to channel's threads

    // ---- time-delay aggregation: warp-uniform taps, clamp-free (padded V) ----
    float* ot = (float*)z;                      // [CHB][OTS] floats
    {
        float wr[TOPK];
        int   ir[TOPK];
        #pragma unroll
        for (int i = 0; i < TOPK; ++i) { wr[i] = w_sh[ch][i]; ir[i] = i_sh[ch][i]; }
        const float* vc = vf + ch * VSTR;
        float* oc = ot + ch * OTS;
        #pragma unroll
        for (int j = 0; j < 16; j += 4) {
            int t0 = u + 64 * j;
            float a0 = 0.f, a1 = 0.f, a2 = 0.f, a3 = 0.f;
            #pragma unroll
            for (int i = 0; i < TOPK; ++i) {
                const float* p = vc + (ir[i] + t0);
                a0 = fmaf(wr[i], p[0],   a0);
                a1 = fmaf(wr[i], p[64],  a1);
                a2 = fmaf(wr[i], p[128], a2);
                a3 = fmaf(wr[i], p[192], a3);
            }
            oc[t0]       = a0;
            oc[t0 + 64]  = a1;
            oc[t0 + 128] = a2;
            oc[t0 + 192] = a3;
        }
    }
    __syncthreads();   // cross-channel: writer reads all channels' staging

    // ---- coalesced float4 write-out from the staging tile ----
    for (int t = tid; t < SEQL; t += NTHREADS) {
        float4 o4;
        o4.x = ot[0 * OTS + t];
        o4.y = ot[1 * OTS + t];
        o4.z = ot[2 * OTS + t];
        o4.w = ot[3 * OTS + t];
        *(float4*)(out + base + (size_t)t * DM) = o4;
    }
}

extern "C" void kernel_launch(void* const* d_in, const int* in_sizes, int n_in,
                              void* d_out, int out_size)
{
    const float* Q = (const float*)d_in[0];
    const float* K = (const float*)d_in[1];
    const float* V = (const float*)d_in[2];
    float* out = (float*)d_out;

    const size_t smem = (size_t)(CHB * ZS) * sizeof(float2)
                      + (size_t)(CHB * VSTR) * sizeof(float);   // 65,632 B
    cudaFuncSetAttribute(autocorr_fused_kernel,
                         cudaFuncAttributeMaxDynamicSharedMemorySize, (int)smem);
    autocorr_fused_kernel<<<NCH / CHB, NTHREADS, smem>>>(Q, K, V, out);
}

// round 16
// speedup vs baseline: 1.1155x; 1.1155x over previous
#include <cuda_runtime.h>
#include <math.h>

#define DM      512
#define SEQL    1024
#define NCH     8192
#define CHB     4         // channels per block (2 blocks/SM)
#define TOPK    13
#define NTHREADS 256
#define ZS      1025      // float2 stride per channel
#define VSTR    2052      // padded float stride for V tile (>= 2047, ==4 mod 32)
#define OTS     2050      // float stride for output staging (== ZS*2)

// per-channel barrier: 64 threads (2 warps) of channel ch
#define BAR_CH() asm volatile("bar.sync %0, %1;" :: "r"(ch + 1), "r"(64) : "memory")

__device__ __forceinline__ float2 cmul(float2 a, float2 b) {
    return make_float2(a.x * b.x - a.y * b.y, a.x * b.y + a.y * b.x);
}
// XOR swizzle, 5-bit key
__device__ __forceinline__ int sw(int p) { return p ^ ((p >> 4) & 31); }

// ---- packed f32x2 ops (sm_100+) ----
__device__ __forceinline__ float2 fadd2(float2 a, float2 b) {
    float2 r;
    asm("add.rn.f32x2 %0, %1, %2;"
        : "=l"(reinterpret_cast<unsigned long long&>(r))
        : "l"(reinterpret_cast<unsigned long long&>(a)),
          "l"(reinterpret_cast<unsigned long long&>(b)));
    return r;
}
__device__ __forceinline__ float2 fsub2(float2 a, float2 b) {
    float2 r;
    asm("sub.rn.f32x2 %0, %1, %2;"
        : "=l"(reinterpret_cast<unsigned long long&>(r))
        : "l"(reinterpret_cast<unsigned long long&>(a)),
          "l"(reinterpret_cast<unsigned long long&>(b)));
    return r;
}
__device__ __forceinline__ void ffma2(float2& acc, float2 a, float2 b) {
    asm("fma.rn.f32x2 %0, %1, %2, %0;"
        : "+l"(reinterpret_cast<unsigned long long&>(acc))
        : "l"(reinterpret_cast<unsigned long long&>(a)),
          "l"(reinterpret_cast<unsigned long long&>(b)));
}

// ---- warp argmax via redux.sync (sortable-uint trick) ----
__device__ __forceinline__ unsigned f2sortable(float x) {
    unsigned f = __float_as_uint(x);
    return (f & 0x80000000u) ? ~f : (f | 0x80000000u);
}
__device__ __forceinline__ float sortable2f(unsigned s) {
    unsigned f = (s & 0x80000000u) ? (s ^ 0x80000000u) : ~s;
    return __uint_as_float(f);
}
__device__ __forceinline__ unsigned redux_max_u32(unsigned v) {
    unsigned r;
    asm("redux.sync.max.u32 %0, %1, 0xffffffff;" : "=r"(r) : "r"(v));
    return r;
}
__device__ __forceinline__ int redux_min_s32(int v) {
    int r;
    asm("redux.sync.min.s32 %0, %1, 0xffffffff;" : "=r"(r) : "r"(v));
    return r;
}

// powers W[1..15] from w1 via squaring chain (tree depth 4 -> ILP)
__device__ __forceinline__ void twpow(float2 w1, float2* W) {
    W[1] = w1;
    W[2] = cmul(w1, w1);
    W[4] = cmul(W[2], W[2]);
    W[8] = cmul(W[4], W[4]);
    W[3] = cmul(W[2], W[1]);
    W[5] = cmul(W[4], W[1]);
    W[6] = cmul(W[4], W[2]);
    W[7] = cmul(W[4], W[3]);
    W[9]  = cmul(W[8], W[1]);
    W[10] = cmul(W[8], W[2]);
    W[11] = cmul(W[8], W[3]);
    W[12] = cmul(W[8], W[4]);
    W[13] = cmul(W[8], W[5]);
    W[14] = cmul(W[8], W[6]);
    W[15] = cmul(W[8], W[7]);
}

#define C16 0.9238795325112867f
#define S16 0.3826834323650898f
#define R22 0.7071067811865476f

// forward 4-pt DFT (W4 = -i), packed
__device__ __forceinline__ void dft4f(float2 x0, float2 x1, float2 x2, float2 x3,
                                      float2& y0, float2& y1, float2& y2, float2& y3) {
    float2 sp = fadd2(x0, x2);
    float2 sm = fsub2(x0, x2);
    float2 tp = fadd2(x1, x3);
    float2 tm = fsub2(x1, x3);
    y0 = fadd2(sp, tp);
    y2 = fsub2(sp, tp);
    float2 tn = make_float2(tm.y, -tm.x);   // -i * tm
    y1 = fadd2(sm, tn);                     // sm - i*tm
    y3 = fsub2(sm, tn);                     // sm + i*tm
}
// inverse 4-pt DFT (W4 = +i), packed
__device__ __forceinline__ void dft4i(float2 x0, float2 x1, float2 x2, float2 x3,
                                      float2& y0, float2& y1, float2& y2, float2& y3) {
    float2 sp = fadd2(x0, x2);
    float2 sm = fsub2(x0, x2);
    float2 tp = fadd2(x1, x3);
    float2 tm = fsub2(x1, x3);
    y0 = fadd2(sp, tp);
    y2 = fsub2(sp, tp);
    float2 tn = make_float2(-tm.y, tm.x);   // +i * tm
    y1 = fadd2(sm, tn);                     // sm + i*tm
    y3 = fsub2(sm, tn);                     // sm - i*tm
}

// 16-pt DFT in registers, natural order in/out. fwd: e^{-2pi i a f/16}
__device__ __forceinline__ void dft16f(float2* v) {
    const float2 W[10] = {
        { 1.f, 0.f}, { C16,-S16}, { R22,-R22}, { S16,-C16}, { 0.f,-1.f},
        {-S16,-C16}, {-R22,-R22}, {-C16,-S16}, {-1.f, 0.f}, {-C16, S16}
    };
    float2 u[16];
    #pragma unroll
    for (int a0 = 0; a0 < 4; ++a0) {
        float2 t0, t1, t2, t3;
        dft4f(v[a0], v[a0 + 4], v[a0 + 8], v[a0 + 12], t0, t1, t2, t3);
        u[a0 * 4 + 0] = t0;
        u[a0 * 4 + 1] = cmul(t1, W[a0]);
        u[a0 * 4 + 2] = cmul(t2, W[2 * a0]);
        u[a0 * 4 + 3] = cmul(t3, W[3 * a0]);
    }
    #pragma unroll
    for (int fl = 0; fl < 4; ++fl) {
        float2 y0, y1, y2, y3;
        dft4f(u[0 * 4 + fl], u[1 * 4 + fl], u[2 * 4 + fl], u[3 * 4 + fl], y0, y1, y2, y3);
        v[fl]      = y0;
        v[fl + 4]  = y1;
        v[fl + 8]  = y2;
        v[fl + 12] = y3;
    }
}
// inverse 16-pt: e^{+2pi i a f/16}, unnormalized
__device__ __forceinline__ void dft16i(float2* v) {
    const float2 W[10] = {
        { 1.f, 0.f}, { C16, S16}, { R22, R22}, { S16, C16}, { 0.f, 1.f},
        {-S16, C16}, {-R22, R22}, {-C16, S16}, {-1.f, 0.f}, {-C16,-S16}
    };
    float2 u[16];
    #pragma unroll
    for (int fl = 0; fl < 4; ++fl) {
        float2 t0, t1, t2, t3;
        dft4i(v[fl], v[fl + 4], v[fl + 8], v[fl + 12], t0, t1, t2, t3);
        u[fl * 4 + 0] = t0;
        u[fl * 4 + 1] = cmul(t1, W[fl]);
        u[fl * 4 + 2] = cmul(t2, W[2 * fl]);
        u[fl * 4 + 3] = cmul(t3, W[3 * fl]);
    }
    #pragma unroll
    for (int a0 = 0; a0 < 4; ++a0) {
        float2 y0, y1, y2, y3;
        dft4i(u[0 * 4 + a0], u[1 * 4 + a0], u[2 * 4 + a0], u[3 * 4 + a0], y0, y1, y2, y3);
        v[a0]      = y0;
        v[a0 + 4]  = y1;
        v[a0 + 8]  = y2;
        v[a0 + 12] = y3;
    }
}

// W64^mp twiddle, mp in [0,4), via select chain (no MUFU)
__device__ __forceinline__ float2 w64(int mp, float sgn) {
    float c = (mp == 0) ? 1.0f
            : (mp == 1) ? 0.99518472667219693f
            : (mp == 2) ? 0.98078528040323044f
            :             0.95694033573220882f;
    float s = (mp == 0) ? 0.0f
            : (mp == 1) ? 0.09801714032956060f
            : (mp == 2) ? 0.19509032201612827f
            :             0.29028467725446233f;
    return make_float2(c, sgn * s);
}

extern __shared__ float2 smem_dyn[];

__global__ void __launch_bounds__(NTHREADS, 2) autocorr_fused_kernel(
    const float* __restrict__ Q, const float* __restrict__ K,
    const float* __restrict__ V, float* __restrict__ out)
{
    float2* z = smem_dyn;                       // [CHB][ZS]
    float*  vf = (float*)(smem_dyn + CHB * ZS); // [CHB][VSTR], clamp-padded
    __shared__ float2 cand[CHB][2][2];
    __shared__ float  w_sh[CHB][TOPK + 1];
    __shared__ int    i_sh[CHB][TOPK];

    const int tid = threadIdx.x;
    const int ch  = tid >> 6;                   // 0..3
    const int u   = tid & 63;
    float2* zc = z + ch * ZS;

    const int bc0 = blockIdx.x * CHB;
    const int b   = bc0 >> 9;
    const int c0  = bc0 & (DM - 1);
    const size_t base = (size_t)b * SEQL * DM + c0;

    // ---- load: z = q + i*k (swizzled), prefetch V ----
    for (int t = tid; t < SEQL; t += NTHREADS) {
        size_t off = base + (size_t)t * DM;
        float4 q4 = *(const float4*)(Q + off);
        float4 k4 = *(const float4*)(K + off);
        int st = sw(t);
        z[0 * ZS + st] = make_float2(q4.x, k4.x);
        z[1 * ZS + st] = make_float2(q4.y, k4.y);
        z[2 * ZS + st] = make_float2(q4.z, k4.z);
        z[3 * ZS + st] = make_float2(q4.w, k4.w);
        float4 v4 = *(const float4*)(V + off);
        vf[0 * VSTR + t] = v4.x;
        vf[1 * VSTR + t] = v4.y;
        vf[2 * VSTR + t] = v4.z;
        vf[3 * VSTR + t] = v4.w;
    }
    __syncthreads();   // cross-channel: loader wrote all channels

    // ---- clamp-fill V tail: vf[ch][1024..2047] = V[ch][1023] ----
    {
        float vlast = vf[ch * VSTR + (SEQL - 1)];
        float* vt = vf + ch * VSTR + SEQL;
        #pragma unroll
        for (int j = 0; j < 16; ++j) vt[u + 64 * j] = vlast;
    }

    // P1/IP1 twiddle base: w1p = exp(-i*pi*u/512); IP1 uses conj(w1p)
    float2 w1p;
    {
        float s, c;
        sincospif((float)u * (1.0f / 512.0f), &s, &c);
        w1p = make_float2(c, -s);
    }

    // ---- P1: radix-16 over stride 64, twiddle W1024^{u*f0} ----
    {
        float2 v[16];
        #pragma unroll
        for (int a = 0; a < 16; ++a) v[a] = zc[sw(u + 64 * a)];
        dft16f(v);
        float2 W[16];
        twpow(w1p, W);
        #pragma unroll
        for (int f = 1; f < 16; ++f) v[f] = cmul(v[f], W[f]);
        #pragma unroll
        for (int f = 0; f < 16; ++f) zc[sw(u + 64 * f)] = v[f];
    }
    BAR_CH();

    // ---- P2: radix-16 over stride 4 within 64-blocks, twiddle W64^{m'*f1} ----
    {
        const int blk = u >> 2;
        const int mp  = u & 3;
        const int bas = 64 * blk + mp;
        float2 v[16];
        #pragma unroll
        for (int a = 0; a < 16; ++a) v[a] = zc[sw(bas + 4 * a)];
        dft16f(v);
        float2 W[16];
        twpow(w64(mp, -1.0f), W);
        #pragma unroll
        for (int f = 1; f < 16; ++f) v[f] = cmul(v[f], W[f]);
        #pragma unroll
        for (int f = 0; f < 16; ++f) zc[sw(bas + 4 * f)] = v[f];
    }
    BAR_CH();

    // ---- FUSED: fwd radix-4 + cross-spectrum + inv radix-4, all in registers ----
    {
        const float scl = 1.0f / (float)SEQL;
        #pragma unroll
        for (int unit = 0; unit < 2; ++unit) {
            int c = u + 1 + unit * 64;          // [1,64] / [65,128]
            if (c < 128) {
                int cp = 256 - c;
                int pA = sw((((c  & 15) << 4) | (c  >> 4)) << 2);
                int pB = sw((((cp & 15) << 4) | (cp >> 4)) << 2);
                float2 A[4], B[4];
                dft4f(zc[pA], zc[pA^1], zc[pA^2], zc[pA^3], A[0], A[1], A[2], A[3]);
                dft4f(zc[pB], zc[pB^1], zc[pB^2], zc[pB^3], B[0], B[1], B[2], B[3]);
                #pragma unroll
                for (int k = 0; k < 4; ++k) {
                    float2 Zf = A[k], Zp = B[3 - k];
                    float Qx = 0.5f * (Zf.x + Zp.x), Qy = 0.5f * (Zf.y - Zp.y);
                    float Kx = 0.5f * (Zf.y + Zp.y), Ky = -0.5f * (Zf.x - Zp.x);
                    float Px = (Qx * Kx + Qy * Ky) * scl;
                    float Py = (Qy * Kx - Qx * Ky) * scl;
                    A[k]     = make_float2(Px,  Py);
                    B[3 - k] = make_float2(Px, -Py);
                }
                float2 y0, y1, y2, y3;
                dft4i(A[0], A[1], A[2], A[3], y0, y1, y2, y3);
                zc[pA] = y0; zc[pA^1] = y1; zc[pA^2] = y2; zc[pA^3] = y3;
                dft4i(B[0], B[1], B[2], B[3], y0, y1, y2, y3);
                zc[pB] = y0; zc[pB^1] = y1; zc[pB^2] = y2; zc[pB^3] = y3;
            } else {
                // u==63, unit==1: c=128 self-paired quad (g=8, p=32)
                {
                    int pA = sw(32);
                    float2 A[4];
                    dft4f(zc[pA], zc[pA^1], zc[pA^2], zc[pA^3], A[0], A[1], A[2], A[3]);
                    #pragma unroll
                    for (int k = 0; k < 2; ++k) {
                        float2 Zf = A[k], Zp = A[3 - k];
                        float Qx = 0.5f * (Zf.x + Zp.x), Qy = 0.5f * (Zf.y - Zp.y);
                        float Kx = 0.5f * (Zf.y + Zp.y), Ky = -0.5f * (Zf.x - Zp.x);
                        float Px = (Qx * Kx + Qy * Ky) * scl;
                        float Py = (Qy * Kx - Qx * Ky) * scl;
                        A[k]     = make_float2(Px,  Py);
                        A[3 - k] = make_float2(Px, -Py);
                    }
                    float2 y0, y1, y2, y3;
                    dft4i(A[0], A[1], A[2], A[3], y0, y1, y2, y3);
                    zc[pA] = y0; zc[pA^1] = y1; zc[pA^2] = y2; zc[pA^3] = y3;
                }
                // c=0 quad (g=0, p=0, sw key 0): f={0,256,512,768}
                {
                    float2 A[4];
                    dft4f(zc[0], zc[1], zc[2], zc[3], A[0], A[1], A[2], A[3]);
                    A[0] = make_float2(A[0].x * A[0].y * scl, 0.0f);
                    A[2] = make_float2(A[2].x * A[2].y * scl, 0.0f);
                    {
                        float2 Zf = A[1], Zp = A[3];
                        float Qx = 0.5f * (Zf.x + Zp.x), Qy = 0.5f * (Zf.y - Zp.y);
                        float Kx = 0.5f * (Zf.y + Zp.y), Ky = -0.5f * (Zf.x - Zp.x);
                        float Px = (Qx * Kx + Qy * Ky) * scl;
                        float Py = (Qy * Kx - Qx * Ky) * scl;
                        A[1] = make_float2(Px,  Py);
                        A[3] = make_float2(Px, -Py);
                    }
                    float2 y0, y1, y2, y3;
                    dft4i(A[0], A[1], A[2], A[3], y0, y1, y2, y3);
                    zc[0] = y0; zc[1] = y1; zc[2] = y2; zc[3] = y3;
                }
            }
        }
    }
    BAR_CH();

    // ---- IP2: conj twiddle then inverse radix-16 stride 4 ----
    {
        const int blk = u >> 2;
        const int mp  = u & 3;
        const int bas = 64 * blk + mp;
        float2 v[16];
        #pragma unroll
        for (int f = 0; f < 16; ++f) v[f] = zc[sw(bas + 4 * f)];
        float2 W[16];
        twpow(w64(mp, 1.0f), W);
        #pragma unroll
        for (int f = 1; f < 16; ++f) v[f] = cmul(v[f], W[f]);
        dft16i(v);
        #pragma unroll
        for (int a = 0; a < 16; ++a) zc[sw(bas + 4 * a)] = v[a];
    }
    BAR_CH();

    // ---- IP1: conj twiddle (reuse w1p) then inverse radix-16 stride 64 ----
    float re[16];
    {
        float2 v[16];
        #pragma unroll
        for (int f = 0; f < 16; ++f) v[f] = zc[sw(u + 64 * f)];
        float2 W[16];
        twpow(make_float2(w1p.x, -w1p.y), W);   // conj of P1 base
        #pragma unroll
        for (int f = 1; f < 16; ++f) v[f] = cmul(v[f], W[f]);
        dft16i(v);
        #pragma unroll
        for (int a = 0; a < 16; ++a) re[a] = v[a].x;   // time index = u + 64a
    }

    // ---- top-13: redux.sync argmax, 2 warps per channel, named barriers ----
    {
        const int lane = tid & 31;
        const int wih  = (u >> 5) & 1;
        float lv = re[0]; int lj = 0;
        #pragma unroll
        for (int j2 = 1; j2 < 16; ++j2)
            if (re[j2] > lv) { lv = re[j2]; lj = j2; }
        int li = u + 64 * lj;

        #pragma unroll 1
        for (int r = 0; r < TOPK; ++r) {
            // warp argmax: redux on sortable value, then redux-min on index
            unsigned sv = f2sortable(lv);
            unsigned m  = redux_max_u32(sv);
            int candi   = (sv == m) ? li : 0x7fffffff;
            int bi      = redux_min_s32(candi);
            float bv    = sortable2f(m);

            int par = r & 1;
            if (lane == 0)
                cand[ch][wih][par] = make_float2(bv, __int_as_float(bi));
            BAR_CH();
            float2 c0v = cand[ch][0][par];
            float2 c1v = cand[ch][1][par];
            float wv; int wi;
            int i0 = __float_as_int(c0v.y), i1 = __float_as_int(c1v.y);
            if (c1v.x > c0v.x || (c1v.x == c0v.x && i1 < i0)) { wv = c1v.x; wi = i1; }
            else                                              { wv = c0v.x; wi = i0; }
            if (u == 0) { w_sh[ch][r] = wv; i_sh[ch][r] = wi; }
            if ((wi & 63) == u) {
                re[wi >> 6] = -INFINITY;
                lv = re[0]; lj = 0;
                #pragma unroll
                for (int j2 = 1; j2 < 16; ++j2)
                    if (re[j2] > lv) { lv = re[j2]; lj = j2; }
                li = u + 64 * lj;
            }
        }
        BAR_CH();
        if (u == 0) {
            float m = -INFINITY;
            #pragma unroll
            for (int i = 0; i < TOPK; ++i) m = fmaxf(m, w_sh[ch][i]);
            float e[TOPK]; float ssum = 0.0f;
            #pragma unroll
            for (int i = 0; i < TOPK; ++i) { e[i] = expf(w_sh[ch][i] - m); ssum += e[i]; }
            float inv = 1.0f / ssum;
            #pragma unroll
            for (int i = 0; i < TOPK; ++i) w_sh[ch][i] = e[i] * inv;
        }
    }
    BAR_CH();   // channel's softmax results visible to channel's threads

    // ---- time-delay aggregation: warp-uniform taps, packed f32x2 FMA ----
    float* ot = (float*)z;                      // [CHB][OTS] floats
    {
        float wr[TOPK];
        int   ir[TOPK];
        #pragma unroll
        for (int i = 0; i < TOPK; ++i) { wr[i] = w_sh[ch][i]; ir[i] = i_sh[ch][i]; }
        const float* vc = vf + ch * VSTR;
        float* oc = ot + ch * OTS;
        #pragma unroll
        for (int j = 0; j < 16; j += 4) {
            int t0 = u + 64 * j;
            float2 acc01 = make_float2(0.f, 0.f);
            float2 acc23 = make_float2(0.f, 0.f);
            #pragma unroll
            for (int i = 0; i < TOPK; ++i) {
                const float* p = vc + (ir[i] + t0);
                float2 ws  = make_float2(wr[i], wr[i]);
                float2 v01 = make_float2(p[0],   p[64]);
                float2 v23 = make_float2(p[128], p[192]);
                ffma2(acc01, ws, v01);
                ffma2(acc23, ws, v23);
            }
            oc[t0]       = acc01.x;
            oc[t0 + 64]  = acc01.y;
            oc[t0 + 128] = acc23.x;
            oc[t0 + 192] = acc23.y;
        }
    }
    __syncthreads();   // cross-channel: writer reads all channels' staging

    // ---- coalesced float4 write-out from the staging tile ----
    for (int t = tid; t < SEQL; t += NTHREADS) {
        float4 o4;
        o4.x = ot[0 * OTS + t];
        o4.y = ot[1 * OTS + t];
        o4.z = ot[2 * OTS + t];
        o4.w = ot[3 * OTS + t];
        *(float4*)(out + base + (size_t)t * DM) = o4;
    }
}

extern "C" void kernel_launch(void* const* d_in, const int* in_sizes, int n_in,
                              void* d_out, int out_size)
{
    const float* Q = (const float*)d_in[0];
    const float* K = (const float*)d_in[1];
    const float* V = (const float*)d_in[2];
    float* out = (float*)d_out;

    const size_t smem = (size_t)(CHB * ZS) * sizeof(float2)
                      + (size_t)(CHB * VSTR) * sizeof(float);   // 65,632 B
    cudaFuncSetAttribute(autocorr_fused_kernel,
                         cudaFuncAttributeMaxDynamicSharedMemorySize, (int)smem);
    autocorr_fused_kernel<<<NCH / CHB, NTHREADS, smem>>>(Q, K, V, out);
}